// round 12
// baseline (speedup 1.0000x reference)
#include <cuda_runtime.h>
#include <cuda_fp16.h>

// CapsNet dynamic routing — fused, 2 CTAs/SM; R9 phase 1 + dual-b interleaved
// routing (both b's share every sync; two independent reduction chains).
// x:  [B=256, N=1152, Ci=8]  fp32
// W:  [C=10, N=1152, Ci=8, Co=16] fp32
// out:[C, B, Co] fp32
//
// Prep: W -> fp16 lane-major, uint4 index (((c*36+g32)*8+i)*2+h)*32+nl.
// Main: 384-thread CTA (12 warps), BT=2, launch_bounds(384,2). Phase 1
// computes u with packed fma.rn.f32x2, stores fp16 h-planes per b. Phase 2
// holds BOTH b's priors in registers (3 rows x 16 co x 2 b, packed half2)
// and runs all 3 routing iterations for b0/b1 interleaved: 7 syncthreads
// total (was 13), butterfly shfl reductions, no-max softmax (|logits|<<88).

static constexpr int kB  = 256;
static constexpr int kN  = 1152;
static constexpr int kCi = 8;
static constexpr int kC  = 10;
static constexpr int kCo = 16;
static constexpr int kBT = 2;
static constexpr int kThreads = 384;   // 12 warps
static constexpr int kWarps = 12;
static constexpr int kRows = 3;        // 1152 / 384

static constexpr int kWTotal = kC * kN * kCi * kCo;   // halfs

__device__ __half g_Wt[kWTotal];

struct Smem {
    uint4 u[kBT][2][kN];        // fp16 priors: [b][h][n] -> 8 halfs (co = 8h+j)
    float red[kBT][kWarps][kCo];
    float zsc[kBT][kWarps];
    float vv[kBT][kCo];
};

// ---------------- packed f32x2 helpers --------------------------------------
__device__ __forceinline__ unsigned long long pk2(float a, float b) {
    unsigned long long r;
    asm("mov.b64 %0, {%1, %2};" : "=l"(r) : "f"(a), "f"(b));
    return r;
}
__device__ __forceinline__ unsigned long long fma2(unsigned long long a,
                                                   unsigned long long b,
                                                   unsigned long long c) {
    unsigned long long d;
    asm("fma.rn.f32x2 %0, %1, %2, %3;" : "=l"(d) : "l"(a), "l"(b), "l"(c));
    return d;
}
__device__ __forceinline__ float2 upk2(unsigned long long a) {
    float x, y;
    asm("mov.b64 {%0, %1}, %2;" : "=f"(x), "=f"(y) : "l"(a));
    return make_float2(x, y);
}

// ---------------- prep: coalesced SMEM-transpose + fp16 convert -------------
__global__ __launch_bounds__(256)
void transpose_W_kernel(const float* __restrict__ W) {
    __shared__ __half s[32][136];          // 128 halfs/row + 8 pad
    const int blk = blockIdx.x;            // c*36 + g32
    const int tid = threadIdx.x;

    const float4* src = reinterpret_cast<const float4*>(W) + (size_t)blk * 1024;
    #pragma unroll
    for (int q = 0; q < 4; ++q) {
        const int v  = tid + q * 256;
        float4 f = src[v];
        const int nl  = v >> 5;
        const int col = (v & 31) * 4;
        *reinterpret_cast<__half2*>(&s[nl][col])     = __floats2half2_rn(f.x, f.y);
        *reinterpret_cast<__half2*>(&s[nl][col + 2]) = __floats2half2_rn(f.z, f.w);
    }
    __syncthreads();

    uint4* dst = reinterpret_cast<uint4*>(g_Wt) + (size_t)blk * 512;
    #pragma unroll
    for (int q = 0; q < 2; ++q) {
        const int o  = tid + q * 256;
        const int nl = o & 31;
        const int ih = o >> 5;             // i*2 + h
        dst[o] = *reinterpret_cast<const uint4*>(&s[nl][ih * 8]);
    }
}

// ---------------- helpers ----------------------------------------------------
__device__ __forceinline__ float warp_reduce16(float a[kCo], int lane) {
    #pragma unroll
    for (int b = 0; b < 4; ++b) {
        const int off = 1 << b;
        const bool hi = (lane >> b) & 1;
        const int hh = 16 >> (b + 1);
        #pragma unroll
        for (int i = 0; i < hh; ++i) {
            float send = hi ? a[i] : a[i + hh];
            float recv = __shfl_xor_sync(0xFFFFFFFFu, send, off);
            a[i] = (hi ? a[i + hh] : a[i]) + recv;
        }
    }
    return a[0] + __shfl_xor_sync(0xFFFFFFFFu, a[0], 16);
}

__device__ __forceinline__ int bitrev4(int l) {
    return ((l & 1) << 3) | ((l & 2) << 1) | ((l & 4) >> 1) | ((l & 8) >> 3);
}

// ---------------- main --------------------------------------------------------
__global__ __launch_bounds__(kThreads, 2)
void caps_routing_kernel(const float* __restrict__ x,
                         float* __restrict__ out)
{
    extern __shared__ unsigned char smem_u8[];
    Smem& sm = *reinterpret_cast<Smem*>(smem_u8);

    const int tid  = threadIdx.x;
    const int lane = tid & 31;
    const int wrp  = tid >> 5;           // 0..11
    const int c    = blockIdx.y;
    const int b0   = blockIdx.x * kBT;
    const int corev = bitrev4(lane & 15);

    // ---------------- Phase 1: priors -> fp16 SMEM planes ------------------
    {
        const int h    = wrp & 1;                       // co-oct
        const int ngrp = wrp >> 1;                      // 0..5
        const float4* __restrict__ X4  = reinterpret_cast<const float4*>(x);
        const uint4*  __restrict__ Wt4 = reinterpret_cast<const uint4*>(g_Wt);

        #pragma unroll 1
        for (int p = 0; p < 6; ++p) {
            const int n   = p * 192 + ngrp * 32 + lane;
            const int g32 = p * 6 + ngrp;

            float4 xa0 = X4[(b0 * kN + n) * 2 + 0];
            float4 xb0 = X4[(b0 * kN + n) * 2 + 1];
            float4 xa1 = X4[((b0 + 1) * kN + n) * 2 + 0];
            float4 xb1 = X4[((b0 + 1) * kN + n) * 2 + 1];
            float x0v[8] = {xa0.x, xa0.y, xa0.z, xa0.w, xb0.x, xb0.y, xb0.z, xb0.w};
            float x1v[8] = {xa1.x, xa1.y, xa1.z, xa1.w, xb1.x, xb1.y, xb1.z, xb1.w};

            unsigned long long acc0[4] = {0ull, 0ull, 0ull, 0ull};
            unsigned long long acc1[4] = {0ull, 0ull, 0ull, 0ull};
            const size_t wb = ((size_t)(c * 36 + g32) * 16 + h) * 32 + lane;
            #pragma unroll
            for (int i = 0; i < kCi; ++i) {
                uint4 w = Wt4[wb + (size_t)i * 64];
                const __half2* hp = reinterpret_cast<const __half2*>(&w);
                const unsigned long long xi0 = pk2(x0v[i], x0v[i]);
                const unsigned long long xi1 = pk2(x1v[i], x1v[i]);
                #pragma unroll
                for (int q = 0; q < 4; ++q) {
                    float2 f = __half22float2(hp[q]);
                    unsigned long long wp = pk2(f.x, f.y);
                    acc0[q] = fma2(xi0, wp, acc0[q]);
                    acc1[q] = fma2(xi1, wp, acc1[q]);
                }
            }
            __half2 p0[4], p1[4];
            #pragma unroll
            for (int q = 0; q < 4; ++q) {
                float2 f0 = upk2(acc0[q]);
                float2 f1 = upk2(acc1[q]);
                p0[q] = __floats2half2_rn(f0.x, f0.y);
                p1[q] = __floats2half2_rn(f1.x, f1.y);
            }
            sm.u[0][h][n] = *reinterpret_cast<uint4*>(p0);
            sm.u[1][h][n] = *reinterpret_cast<uint4*>(p1);
        }
    }
    __syncthreads();

    // ---------------- Phase 2: dual-b interleaved routing -------------------
    // Load BOTH b's priors into registers (packed half2, 48 regs).
    __half2 u2[kBT][kRows][8];
    #pragma unroll
    for (int bb = 0; bb < kBT; ++bb) {
        #pragma unroll
        for (int k = 0; k < kRows; ++k) {
            const int n = tid + k * kThreads;
            uint4 lo = sm.u[bb][0][n];
            uint4 hi = sm.u[bb][1][n];
            const __half2* l2 = reinterpret_cast<const __half2*>(&lo);
            const __half2* h2 = reinterpret_cast<const __half2*>(&hi);
            #pragma unroll
            for (int q = 0; q < 4; ++q) { u2[bb][k][q] = l2[q]; u2[bb][k][4+q] = h2[q]; }
        }
    }

    float lg[kBT][kRows];

    // ---- iteration 0: uniform probs (both b) ----
    {
        #pragma unroll
        for (int bb = 0; bb < kBT; ++bb) {
            float r[kCo];
            #pragma unroll
            for (int j = 0; j < 8; ++j) {
                float2 f0 = __half22float2(u2[bb][0][j]);
                float2 f1 = __half22float2(u2[bb][1][j]);
                float2 f2 = __half22float2(u2[bb][2][j]);
                r[2*j]   = f0.x + f1.x + f2.x;
                r[2*j+1] = f0.y + f1.y + f2.y;
            }
            float tot = warp_reduce16(r, lane);
            if (lane < 16) sm.red[bb][wrp][corev] = tot;
        }
        __syncthreads();

        if (tid < 32) {
            const int bb = tid >> 4, co = tid & 15;
            float s = 0.f;
            #pragma unroll
            for (int w = 0; w < kWarps; ++w) s += sm.red[bb][w][co];
            s *= (1.0f / kN);
            float sq = s * s;
            #pragma unroll
            for (int off = 8; off; off >>= 1)
                sq += __shfl_xor_sync(0xFFFFFFFFu, sq, off);
            sm.vv[bb][co] = s * sqrtf(sq) / (1.0f + sq);
        }
        __syncthreads();

        #pragma unroll
        for (int bb = 0; bb < kBT; ++bb) {
            float v[kCo];
            #pragma unroll
            for (int co = 0; co < kCo; ++co) v[co] = sm.vv[bb][co];
            #pragma unroll
            for (int k = 0; k < kRows; ++k) {
                float d = 0.f;
                #pragma unroll
                for (int j = 0; j < 8; ++j) {
                    float2 f = __half22float2(u2[bb][k][j]);
                    d += f.x * v[2*j] + f.y * v[2*j+1];
                }
                lg[bb][k] = d;
            }
        }
    }

    // ---- iterations 1, 2 (no-max softmax: |logits| << 88) ----
    #pragma unroll 1
    for (int it = 1; it < 3; ++it) {
        #pragma unroll
        for (int bb = 0; bb < kBT; ++bb) {
            float e[kRows];
            float zp = 0.f;
            #pragma unroll
            for (int k = 0; k < kRows; ++k) {
                e[k] = __expf(lg[bb][k]);
                zp += e[k];
            }
            #pragma unroll
            for (int off = 16; off; off >>= 1)
                zp += __shfl_xor_sync(0xFFFFFFFFu, zp, off);

            float r[kCo];
            #pragma unroll
            for (int j = 0; j < 8; ++j) {
                float2 f0 = __half22float2(u2[bb][0][j]);
                float2 f1 = __half22float2(u2[bb][1][j]);
                float2 f2 = __half22float2(u2[bb][2][j]);
                r[2*j]   = e[0]*f0.x + e[1]*f1.x + e[2]*f2.x;
                r[2*j+1] = e[0]*f0.y + e[1]*f1.y + e[2]*f2.y;
            }
            float tot = warp_reduce16(r, lane);
            if (lane == 0) sm.zsc[bb][wrp] = zp;
            if (lane < 16) sm.red[bb][wrp][corev] = tot;
        }
        __syncthreads();

        if (tid < 32) {
            const int bb = tid >> 4, co = tid & 15;
            float Z = 0.f, s = 0.f;
            #pragma unroll
            for (int w = 0; w < kWarps; ++w) { Z += sm.zsc[bb][w]; s += sm.red[bb][w][co]; }
            s = __fdividef(s, Z);
            float sq = s * s;
            #pragma unroll
            for (int off = 8; off; off >>= 1)
                sq += __shfl_xor_sync(0xFFFFFFFFu, sq, off);
            float v = s * sqrtf(sq) / (1.0f + sq);
            sm.vv[bb][co] = v;
            if (it == 2)
                out[(c * kB + b0 + bb) * kCo + co] = v;
        }
        __syncthreads();

        if (it == 1) {
            #pragma unroll
            for (int bb = 0; bb < kBT; ++bb) {
                float v[kCo];
                #pragma unroll
                for (int co = 0; co < kCo; ++co) v[co] = sm.vv[bb][co];
                #pragma unroll
                for (int k = 0; k < kRows; ++k) {
                    float d = 0.f;
                    #pragma unroll
                    for (int j = 0; j < 8; ++j) {
                        float2 f = __half22float2(u2[bb][k][j]);
                        d += f.x * v[2*j] + f.y * v[2*j+1];
                    }
                    lg[bb][k] += d;
                }
            }
        }
    }
}

extern "C" void kernel_launch(void* const* d_in, const int* in_sizes, int n_in,
                              void* d_out, int out_size)
{
    const float* x = (const float*)d_in[0];
    const float* W = (const float*)d_in[1];
    float* out = (float*)d_out;

    transpose_W_kernel<<<kC * 36, 256>>>(W);

    cudaFuncSetAttribute(caps_routing_kernel,
                         cudaFuncAttributeMaxDynamicSharedMemorySize,
                         (int)sizeof(Smem));
    dim3 grid(kB / kBT, kC);
    caps_routing_kernel<<<grid, kThreads, sizeof(Smem)>>>(x, out);
}

// round 13
// speedup vs baseline: 1.2431x; 1.2431x over previous
#include <cuda_runtime.h>
#include <cuda_fp16.h>

// CapsNet dynamic routing — fused, 2 CTAs/SM. R9 phase 1 + distributed-squash
// routing: every warp redundantly computes the squash from per-warp partials,
// eliminating the single-warp bubble and halving syncthreads (13 -> 7).
// Scratch (red/zsc) is double-buffered; b0 uses buffer seq 0,1,0 and b1 uses
// 1,0,1 so no extra syncs are needed for WAR safety.
// x:  [B=256, N=1152, Ci=8]  fp32
// W:  [C=10, N=1152, Ci=8, Co=16] fp32
// out:[C, B, Co] fp32

static constexpr int kB  = 256;
static constexpr int kN  = 1152;
static constexpr int kCi = 8;
static constexpr int kC  = 10;
static constexpr int kCo = 16;
static constexpr int kBT = 2;
static constexpr int kThreads = 384;   // 12 warps
static constexpr int kWarps = 12;
static constexpr int kRows = 3;        // 1152 / 384

static constexpr int kWTotal = kC * kN * kCi * kCo;   // halfs

__device__ __half g_Wt[kWTotal];

struct Smem {
    uint4 u[kBT][2][kN];        // fp16 priors: [b][h][n] -> 8 halfs (co = 8h+j)
    float red[2][kWarps][kCo];  // double-buffered per-warp s partials
    float zsc[2][kWarps];       // double-buffered per-warp Z partials
};

// ---------------- packed f32x2 helpers --------------------------------------
__device__ __forceinline__ unsigned long long pk2(float a, float b) {
    unsigned long long r;
    asm("mov.b64 %0, {%1, %2};" : "=l"(r) : "f"(a), "f"(b));
    return r;
}
__device__ __forceinline__ unsigned long long fma2(unsigned long long a,
                                                   unsigned long long b,
                                                   unsigned long long c) {
    unsigned long long d;
    asm("fma.rn.f32x2 %0, %1, %2, %3;" : "=l"(d) : "l"(a), "l"(b), "l"(c));
    return d;
}
__device__ __forceinline__ float2 upk2(unsigned long long a) {
    float x, y;
    asm("mov.b64 {%0, %1}, %2;" : "=f"(x), "=f"(y) : "l"(a));
    return make_float2(x, y);
}

// ---------------- prep: coalesced SMEM-transpose + fp16 convert -------------
__global__ __launch_bounds__(256)
void transpose_W_kernel(const float* __restrict__ W) {
    __shared__ __half s[32][136];          // 128 halfs/row + 8 pad
    const int blk = blockIdx.x;            // c*36 + g32
    const int tid = threadIdx.x;

    const float4* src = reinterpret_cast<const float4*>(W) + (size_t)blk * 1024;
    #pragma unroll
    for (int q = 0; q < 4; ++q) {
        const int v  = tid + q * 256;
        float4 f = src[v];
        const int nl  = v >> 5;
        const int col = (v & 31) * 4;
        *reinterpret_cast<__half2*>(&s[nl][col])     = __floats2half2_rn(f.x, f.y);
        *reinterpret_cast<__half2*>(&s[nl][col + 2]) = __floats2half2_rn(f.z, f.w);
    }
    __syncthreads();

    uint4* dst = reinterpret_cast<uint4*>(g_Wt) + (size_t)blk * 512;
    #pragma unroll
    for (int q = 0; q < 2; ++q) {
        const int o  = tid + q * 256;
        const int nl = o & 31;
        const int ih = o >> 5;             // i*2 + h
        dst[o] = *reinterpret_cast<const uint4*>(&s[nl][ih * 8]);
    }
}

// ---------------- helpers ----------------------------------------------------
__device__ __forceinline__ float warp_reduce16(float a[kCo], int lane) {
    #pragma unroll
    for (int b = 0; b < 4; ++b) {
        const int off = 1 << b;
        const bool hi = (lane >> b) & 1;
        const int hh = 16 >> (b + 1);
        #pragma unroll
        for (int i = 0; i < hh; ++i) {
            float send = hi ? a[i] : a[i + hh];
            float recv = __shfl_xor_sync(0xFFFFFFFFu, send, off);
            a[i] = (hi ? a[i + hh] : a[i]) + recv;
        }
    }
    return a[0] + __shfl_xor_sync(0xFFFFFFFFu, a[0], 16);
}

__device__ __forceinline__ int bitrev4(int l) {
    return ((l & 1) << 3) | ((l & 2) << 1) | ((l & 4) >> 1) | ((l & 8) >> 3);
}

// Distributed squash: given this thread's co-partial sum already in red[buf]
// (and Z in zsc[buf] when useZ), every warp computes v for co = corev(lane).
// Returns vown; caller broadcasts if needed. ONE sync per stage.
__device__ __forceinline__ float squash_stage(
    Smem& sm, int buf, int corev, bool useZ, float normK)
{
    float s = 0.f, Z = 0.f;
    #pragma unroll
    for (int w = 0; w < kWarps; ++w) {
        s += sm.red[buf][w][corev];
        if (useZ) Z += sm.zsc[buf][w];
    }
    s = useZ ? __fdividef(s, Z) : s * normK;
    float sq = s * s;
    #pragma unroll
    for (int off = 8; off; off >>= 1)
        sq += __shfl_xor_sync(0xFFFFFFFFu, sq, off);   // within 16-lane co-group
    return s * sqrtf(sq) / (1.0f + sq);
}

// Routing for one b on register-resident packed u. bufbase in {0,1}:
// iteration i uses scratch buffer bufbase ^ (i & 1).
__device__ __forceinline__ void route_one(
    Smem& sm, const __half2 u2[kRows][8],
    int lane, int wrp, int corev,
    float* __restrict__ outp, int bufbase)
{
    float lg[kRows];

    // ---- iteration 0: uniform probs ----
    {
        float r[kCo];
        #pragma unroll
        for (int j = 0; j < 8; ++j) {
            float2 f0 = __half22float2(u2[0][j]);
            float2 f1 = __half22float2(u2[1][j]);
            float2 f2 = __half22float2(u2[2][j]);
            r[2*j]   = f0.x + f1.x + f2.x;
            r[2*j+1] = f0.y + f1.y + f2.y;
        }
        float tot = warp_reduce16(r, lane);
        const int buf = bufbase;
        if (lane < 16) sm.red[buf][wrp][corev] = tot;
        __syncthreads();

        float vown = squash_stage(sm, buf, corev, false, 1.0f / kN);

        float v[kCo];
        #pragma unroll
        for (int j = 0; j < kCo; ++j)
            v[j] = __shfl_sync(0xFFFFFFFFu, vown, bitrev4(j));
        #pragma unroll
        for (int k = 0; k < kRows; ++k) {
            float d = 0.f;
            #pragma unroll
            for (int j = 0; j < 8; ++j) {
                float2 f = __half22float2(u2[k][j]);
                d += f.x * v[2*j] + f.y * v[2*j+1];
            }
            lg[k] = d;
        }
    }

    // ---- iterations 1, 2 (no-max softmax: |logits| << 88) ----
    #pragma unroll 1
    for (int it = 1; it < 3; ++it) {
        float e[kRows];
        float zp = 0.f;
        #pragma unroll
        for (int k = 0; k < kRows; ++k) {
            e[k] = __expf(lg[k]);
            zp += e[k];
        }
        #pragma unroll
        for (int off = 16; off; off >>= 1)
            zp += __shfl_xor_sync(0xFFFFFFFFu, zp, off);

        float r[kCo];
        #pragma unroll
        for (int j = 0; j < 8; ++j) {
            float2 f0 = __half22float2(u2[0][j]);
            float2 f1 = __half22float2(u2[1][j]);
            float2 f2 = __half22float2(u2[2][j]);
            r[2*j]   = e[0]*f0.x + e[1]*f1.x + e[2]*f2.x;
            r[2*j+1] = e[0]*f0.y + e[1]*f1.y + e[2]*f2.y;
        }
        float tot = warp_reduce16(r, lane);
        const int buf = bufbase ^ (it & 1);
        if (lane == 0) sm.zsc[buf][wrp] = zp;
        if (lane < 16) sm.red[buf][wrp][corev] = tot;
        __syncthreads();

        float vown = squash_stage(sm, buf, corev, true, 0.f);

        if (it == 2) {
            if (wrp == 0 && lane < 16)
                outp[corev] = vown;
        } else {
            float v[kCo];
            #pragma unroll
            for (int j = 0; j < kCo; ++j)
                v[j] = __shfl_sync(0xFFFFFFFFu, vown, bitrev4(j));
            #pragma unroll
            for (int k = 0; k < kRows; ++k) {
                float d = 0.f;
                #pragma unroll
                for (int j = 0; j < 8; ++j) {
                    float2 f = __half22float2(u2[k][j]);
                    d += f.x * v[2*j] + f.y * v[2*j+1];
                }
                lg[k] += d;
            }
        }
    }
}

// ---------------- main --------------------------------------------------------
__global__ __launch_bounds__(kThreads, 2)
void caps_routing_kernel(const float* __restrict__ x,
                         float* __restrict__ out)
{
    extern __shared__ unsigned char smem_u8[];
    Smem& sm = *reinterpret_cast<Smem*>(smem_u8);

    const int tid  = threadIdx.x;
    const int lane = tid & 31;
    const int wrp  = tid >> 5;           // 0..11
    const int c    = blockIdx.y;
    const int b0   = blockIdx.x * kBT;
    const int corev = bitrev4(lane & 15);

    // ---------------- Phase 1: priors -> fp16 SMEM planes ------------------
    {
        const int h    = wrp & 1;                       // co-oct
        const int ngrp = wrp >> 1;                      // 0..5
        const float4* __restrict__ X4  = reinterpret_cast<const float4*>(x);
        const uint4*  __restrict__ Wt4 = reinterpret_cast<const uint4*>(g_Wt);

        #pragma unroll 1
        for (int p = 0; p < 6; ++p) {
            const int n   = p * 192 + ngrp * 32 + lane;
            const int g32 = p * 6 + ngrp;

            float4 xa0 = X4[(b0 * kN + n) * 2 + 0];
            float4 xb0 = X4[(b0 * kN + n) * 2 + 1];
            float4 xa1 = X4[((b0 + 1) * kN + n) * 2 + 0];
            float4 xb1 = X4[((b0 + 1) * kN + n) * 2 + 1];
            float x0v[8] = {xa0.x, xa0.y, xa0.z, xa0.w, xb0.x, xb0.y, xb0.z, xb0.w};
            float x1v[8] = {xa1.x, xa1.y, xa1.z, xa1.w, xb1.x, xb1.y, xb1.z, xb1.w};

            unsigned long long acc0[4] = {0ull, 0ull, 0ull, 0ull};
            unsigned long long acc1[4] = {0ull, 0ull, 0ull, 0ull};
            const size_t wb = ((size_t)(c * 36 + g32) * 16 + h) * 32 + lane;
            #pragma unroll
            for (int i = 0; i < kCi; ++i) {
                uint4 w = Wt4[wb + (size_t)i * 64];
                const __half2* hp = reinterpret_cast<const __half2*>(&w);
                const unsigned long long xi0 = pk2(x0v[i], x0v[i]);
                const unsigned long long xi1 = pk2(x1v[i], x1v[i]);
                #pragma unroll
                for (int q = 0; q < 4; ++q) {
                    float2 f = __half22float2(hp[q]);
                    unsigned long long wp = pk2(f.x, f.y);
                    acc0[q] = fma2(xi0, wp, acc0[q]);
                    acc1[q] = fma2(xi1, wp, acc1[q]);
                }
            }
            __half2 p0[4], p1[4];
            #pragma unroll
            for (int q = 0; q < 4; ++q) {
                float2 f0 = upk2(acc0[q]);
                float2 f1 = upk2(acc1[q]);
                p0[q] = __floats2half2_rn(f0.x, f0.y);
                p1[q] = __floats2half2_rn(f1.x, f1.y);
            }
            sm.u[0][h][n] = *reinterpret_cast<uint4*>(p0);
            sm.u[1][h][n] = *reinterpret_cast<uint4*>(p1);
        }
    }
    __syncthreads();

    // ---------------- Phase 2: routing, sequential over b ------------------
    #pragma unroll 1
    for (int bb = 0; bb < kBT; ++bb) {
        __half2 u2[kRows][8];
        #pragma unroll
        for (int k = 0; k < kRows; ++k) {
            const int n = tid + k * kThreads;
            uint4 lo = sm.u[bb][0][n];
            uint4 hi = sm.u[bb][1][n];
            const __half2* l2 = reinterpret_cast<const __half2*>(&lo);
            const __half2* h2 = reinterpret_cast<const __half2*>(&hi);
            #pragma unroll
            for (int q = 0; q < 4; ++q) { u2[k][q] = l2[q]; u2[k][4+q] = h2[q]; }
        }

        // b0 uses scratch buffers (0,1,0); b1 uses (1,0,1) -> WAR-safe with
        // exactly one sync per stage.
        route_one(sm, u2, lane, wrp, corev,
                  out + (c * kB + b0 + bb) * kCo, bb);
    }
}

extern "C" void kernel_launch(void* const* d_in, const int* in_sizes, int n_in,
                              void* d_out, int out_size)
{
    const float* x = (const float*)d_in[0];
    const float* W = (const float*)d_in[1];
    float* out = (float*)d_out;

    transpose_W_kernel<<<kC * 36, 256>>>(W);

    cudaFuncSetAttribute(caps_routing_kernel,
                         cudaFuncAttributeMaxDynamicSharedMemorySize,
                         (int)sizeof(Smem));
    dim3 grid(kB / kBT, kC);
    caps_routing_kernel<<<grid, kThreads, sizeof(Smem)>>>(x, out);
}